// round 11
// baseline (speedup 1.0000x reference)
#include <cuda_runtime.h>
#include <cuda_fp16.h>
#include <cstdint>

#define HH 96
#define WW 96
#define CC 256
#define NP (HH*WW)          // 9216 pixels per image
#define NB 2
#define HP 98
#define PADP (HP*HP)        // 9604 padded pixels
#define NOUT 2048           // GEMM N: 1536 (Z) + 432 (guidance taps) + 80 pad
#define NGUID 1536
#define NTOT 18432.0f

// ---------------- static scratch ----------------
__device__ __half g_A[(size_t)NB*PADP*CC];      // padded NHWC x, fp16 (ring never read)
__device__ __half g_B[(size_t)NOUT*CC];         // [W_t ; tap weights] fp16
__device__ __half g_Z[(size_t)NB*NP*NOUT];      // GEMM output, fp16
__device__ float g_w[(size_t)NB*NP*48];         // softmaxed dynamic weights
__device__ float g_y[(size_t)NB*NP*CC];         // pre-BN output, NHWC
__device__ float g_stats[512];
__device__ float g_scale[CC];
__device__ float g_shift[CC];

// ================= helpers =================
__device__ __forceinline__ uint32_t smem_u32(const void* p) {
    uint32_t a;
    asm("{ .reg .u64 t; cvta.to.shared.u64 t, %1; cvt.u32.u64 %0, t; }" : "=r"(a) : "l"(p));
    return a;
}
#define SWZ128(o) ((o) ^ (((o) >> 3) & 0x70))

__device__ __forceinline__ void ldsm_x4(uint32_t& r0, uint32_t& r1, uint32_t& r2, uint32_t& r3,
                                        uint32_t addr) {
    asm volatile("ldmatrix.sync.aligned.m8n8.x4.shared.b16 {%0,%1,%2,%3}, [%4];"
                 : "=r"(r0), "=r"(r1), "=r"(r2), "=r"(r3) : "r"(addr));
}
__device__ __forceinline__ void mma16816(float* d, const uint32_t* a, const uint32_t* b) {
    asm volatile("mma.sync.aligned.m16n8k16.row.col.f32.f16.f16.f32 "
                 "{%0,%1,%2,%3}, {%4,%5,%6,%7}, {%8,%9}, {%0,%1,%2,%3};"
                 : "+f"(d[0]), "+f"(d[1]), "+f"(d[2]), "+f"(d[3])
                 : "r"(a[0]), "r"(a[1]), "r"(a[2]), "r"(a[3]), "r"(b[0]), "r"(b[1]));
}
__device__ __forceinline__ void cpasync16(uint32_t dst, const void* src) {
    asm volatile("cp.async.cg.shared.global [%0], [%1], 16;" :: "r"(dst), "l"(src));
}
#define CP_COMMIT() asm volatile("cp.async.commit_group;" ::: "memory")
#define CP_WAIT(n)  asm volatile("cp.async.wait_group %0;" :: "n"(n) : "memory")

// ---------------- zero stats ----------------
__global__ void k_zero_stats() {
    int t = blockIdx.x*256 + threadIdx.x;
    if (t < 512) g_stats[t] = 0.f;
}

// ---------------- NCHW -> padded NHWC fp16 ----------------
__global__ void k_pad_split(const float* __restrict__ x) {
    __shared__ float tile[32][33];
    int n  = blockIdx.z >> 3;
    int c0 = (blockIdx.z & 7) * 32;
    int y  = blockIdx.y;
    int x0 = blockIdx.x * 32;
    int tx = threadIdx.x, ty = threadIdx.y;
#pragma unroll
    for (int i = 0; i < 4; i++) {
        int c = c0 + ty + i*8;
        tile[ty + i*8][tx] = x[(((size_t)n*CC + c)*HH + y)*WW + x0 + tx];
    }
    __syncthreads();
#pragma unroll
    for (int i = 0; i < 4; i++) {
        int xl = ty + i*8;
        int c  = c0 + tx;
        size_t idx = ((size_t)n*PADP + (size_t)(y+1)*HP + (x0 + xl + 1))*CC + c;
        g_A[idx] = __float2half(tile[tx][xl]);
    }
}

// ---------------- build B = [W_t ; tap weights], fp16 ----------------
__global__ void k_wsplit(const float* __restrict__ ws, const float* __restrict__ wcat) {
    int i = blockIdx.x*256 + threadIdx.x;   // over NOUT*CC
    int mp = i >> 8, c = i & 255;
    float v = 0.f;
    if (mp < NGUID) {
        int o = mp & 255, j = mp >> 8;
        v = ws[(size_t)o*NGUID + j*256 + c];
    } else if (mp < NGUID + 432) {
        int t = mp - NGUID, tap = t / 48, oc = t % 48;
        if (oc < 45) v = wcat[((size_t)(oc*256 + c))*9 + tap];
    }
    g_B[i] = __float2half(v);
}

// ---------------- warp-MMA GEMM, cp.async double-buffered, single fp16 ----------------
// Stage (32 KB): A 16K | B 16K. Two stages = 64 KB -> 3 CTAs/SM.
#define SM_A   0
#define SM_B   16384
#define STAGE_SZ 32768
#define SM_TOTAL (2*STAGE_SZ)

__global__ __launch_bounds__(256, 3) void k_gemm() {
    extern __shared__ char smem[];
    uint32_t smemu = smem_u32(smem);
    int tid = threadIdx.x, wid = tid >> 5, lane = tid & 31;
    int n  = blockIdx.z;
    int pb = blockIdx.x * 128;
    int nb = blockIdx.y * 128;

    // ---- loader mapping: thread -> (row r, half); 4x16B per array per chunk ----
    int r = tid >> 1;
    int half_ = tid & 1;
    int p  = pb + r;
    int py = p / WW, px = p % WW;
    size_t aoff = ((size_t)n*PADP + (size_t)(py+1)*HP + (px+1))*CC + half_*32;
    size_t boff = (size_t)(nb + r)*CC + half_*32;
    uint32_t so[4];
#pragma unroll
    for (int i = 0; i < 4; i++) {
        uint32_t o = (uint32_t)(r*128 + half_*64 + i*16);
        so[i] = SWZ128(o);
    }

    // ---- warp tile mapping: 4 warps over M (32 each), 2 over N (64 each) ----
    int wm = wid & 3, wn = wid >> 2;

    uint32_t xorv = (uint32_t)((lane & 7) << 4);
    int a_row0 = wm*32 + ((lane >> 3) & 1)*8 + (lane & 7);
    uint32_t a_colsel = (uint32_t)((lane >> 4) * 16);
    int b_row0 = wn*64 + ((lane >> 4))*8 + (lane & 7);
    uint32_t b_colsel = (uint32_t)(((lane >> 3) & 1) * 16);

    uint32_t aB0 = smemu + SM_A + (uint32_t)(a_row0*128);
    uint32_t aB1 = aB0 + 16*128;
    uint32_t bB  = smemu + SM_B + (uint32_t)(b_row0*128);

    float acc[2][8][4];
#pragma unroll
    for (int t = 0; t < 2; t++)
#pragma unroll
        for (int q = 0; q < 8; q++)
#pragma unroll
            for (int e = 0; e < 4; e++) acc[t][q][e] = 0.f;

    auto issue = [&](int kc, int stage) {
        uint32_t sb = smemu + (uint32_t)stage*STAGE_SZ;
        const uint4* pa = (const uint4*)(g_A + aoff + kc*64);
        const uint4* pb_ = (const uint4*)(g_B + boff + kc*64);
#pragma unroll
        for (int i = 0; i < 4; i++) {
            cpasync16(sb + SM_A + so[i], pa  + i);
            cpasync16(sb + SM_B + so[i], pb_ + i);
        }
    };

    issue(0, 0);
    CP_COMMIT();

    for (int kc = 0; kc < 4; kc++) {
        if (kc < 3) {
            issue(kc + 1, (kc + 1) & 1);
            CP_COMMIT();
            CP_WAIT(1);
        } else {
            CP_WAIT(0);
        }
        __syncthreads();

        uint32_t soff = (uint32_t)(kc & 1) * STAGE_SZ;
#pragma unroll
        for (int ks = 0; ks < 4; ks++) {
            uint32_t aoffs = ((uint32_t)(ks*32) + a_colsel) ^ xorv;
            uint32_t boffs = ((uint32_t)(ks*32) + b_colsel) ^ xorv;

            uint32_t ah[2][4];
            ldsm_x4(ah[0][0], ah[0][1], ah[0][2], ah[0][3], aB0 + soff + aoffs);
            ldsm_x4(ah[1][0], ah[1][1], ah[1][2], ah[1][3], aB1 + soff + aoffs);

#pragma unroll
            for (int qp = 0; qp < 4; qp++) {
                uint32_t bh[4];
                ldsm_x4(bh[0], bh[1], bh[2], bh[3], bB + soff + (uint32_t)(qp*16*128) + boffs);
                int q0 = qp*2, q1 = qp*2 + 1;
                mma16816(acc[0][q0], ah[0], bh + 0);
                mma16816(acc[1][q0], ah[1], bh + 0);
                mma16816(acc[0][q1], ah[0], bh + 2);
                mma16816(acc[1][q1], ah[1], bh + 2);
            }
        }
        __syncthreads();
    }

    // ---- epilogue: write fragments to g_Z as fp16 ----
#pragma unroll
    for (int t = 0; t < 2; t++) {
        size_t row = (size_t)n*NP + pb + wm*32 + t*16 + (lane >> 2);
        __half* zbase = g_Z + row*NOUT + nb + wn*64 + (lane & 3)*2;
#pragma unroll
        for (int q = 0; q < 8; q++) {
            *(__half2*)(zbase + q*8)          = __floats2half2_rn(acc[t][q][0], acc[t][q][1]);
            *(__half2*)(zbase + q*8 + 8*NOUT) = __floats2half2_rn(acc[t][q][2], acc[t][q][3]);
        }
    }
}

// ---------------- fused guidance shifted-sum + softmax ----------------
__global__ void k_guid() {
    int i = blockIdx.x*256 + threadIdx.x;    // over NB*NP*5
    if (i >= NB*NP*5) return;
    int br = i % 5;
    int P  = i / 5;
    int n  = P / NP, p = P % NP;
    int py = p / WW, px = p % WW;

    float v[9];
#pragma unroll
    for (int k = 0; k < 9; k++) v[k] = 0.f;
#pragma unroll
    for (int tap = 0; tap < 9; tap++) {
        int dy = tap/3 - 1, dx = tap%3 - 1;
        int qy = py + dy, qx = px + dx;
        if ((unsigned)qy < HH && (unsigned)qx < WW) {
            const __half* zr = g_Z + ((size_t)n*NP + qy*WW + qx)*NOUT + NGUID + tap*48 + br*9;
#pragma unroll
            for (int k = 0; k < 9; k++) v[k] += __half2float(zr[k]);
        }
    }
    float m = -1e30f;
#pragma unroll
    for (int k = 0; k < 9; k++) m = fmaxf(m, v[k]);
    float s = 0.f;
#pragma unroll
    for (int k = 0; k < 9; k++) { v[k] = __expf(v[k] - m); s += v[k]; }
    float inv = 1.f / s;
    float* row = g_w + (size_t)P*48 + 9*br;
#pragma unroll
    for (int k = 0; k < 9; k++) row[k] = v[k] * inv;
}

// ---------------- gather + fused BN-stats ----------------
__device__ __forceinline__ void h8_fma(float* A, uint4 raw, float w) {
    __half2* h = (__half2*)&raw;
#pragma unroll
    for (int j = 0; j < 4; j++) {
        float2 f = __half22float2(h[j]);
        A[j*2+0] += w * f.x;
        A[j*2+1] += w * f.y;
    }
}

__global__ __launch_bounds__(256) void k_gather() {
    __shared__ float wsh[8][48];
    __shared__ float ssum[256], ssq[256];
    int tid = threadIdx.x;
    int warp = tid >> 5, lane = tid & 31;
    ssum[tid] = 0.f; ssq[tid] = 0.f;

    int P = blockIdx.x*8 + warp;
    int n = P / NP, p = P % NP;
    int py = p / WW, px = p % WW;

    const float* wrow = g_w + (size_t)P*48;
    if (lane < 45) wsh[warp][lane] = wrow[lane];
    if (lane < 13) wsh[warp][32 + lane] = wrow[32 + lane];
    __syncthreads();

    float A[8];
    {
        uint4 raw = *(const uint4*)(g_Z + (size_t)P*NOUT + lane*8);
        __half2* h = (__half2*)&raw;
#pragma unroll
        for (int j = 0; j < 4; j++) {
            float2 f = __half22float2(h[j]);
            A[j*2+0] = f.x;
            A[j*2+1] = f.y;
        }
    }

    const int DS[5] = {1, 6, 12, 24, 36};
#pragma unroll
    for (int br = 0; br < 5; ++br) {
        int d = DS[br];
#pragma unroll
        for (int k = 0; k < 9; k++) {
            int dy = (k/3 - 1)*d, dx = (k%3 - 1)*d;
            int ny = py + dy, nx = px + dx;
            if ((unsigned)ny < HH && (unsigned)nx < WW) {
                float w = wsh[warp][br*9 + k];
                uint4 raw = *(const uint4*)(g_Z + ((size_t)n*NP + ny*WW + nx)*NOUT + (br+1)*256 + lane*8);
                h8_fma(A, raw, w);
            }
        }
    }

    float* yr = g_y + (size_t)P*CC + lane*8;
#pragma unroll
    for (int j = 0; j < 8; j++) yr[j] = A[j];

    // fused BN stats: smem accumulate then one global atomic per channel
#pragma unroll
    for (int j = 0; j < 8; j++) {
        atomicAdd(&ssum[lane*8 + j], A[j]);
        atomicAdd(&ssq[lane*8 + j], A[j]*A[j]);
    }
    __syncthreads();
    if (warp < 4) {
        int c = tid;
        atomicAdd(&g_stats[c], ssum[c]);
        atomicAdd(&g_stats[256 + c], ssq[c]);
        c = tid + 128;
        atomicAdd(&g_stats[c], ssum[c]);
        atomicAdd(&g_stats[256 + c], ssq[c]);
    }
}

__global__ void k_finalize(const float* __restrict__ gamma, const float* __restrict__ beta) {
    int t = threadIdx.x;
    float mean = g_stats[t] / NTOT;
    float var  = g_stats[256 + t] / NTOT - mean*mean;
    float rstd = rsqrtf(var + 1e-5f);
    float sc = gamma[t] * rstd;
    g_scale[t] = sc;
    g_shift[t] = beta[t] - mean*sc;
}

// ---------------- affine + NHWC -> NCHW ----------------
__global__ void k_norm(float* __restrict__ out) {
    __shared__ float tile[32][33];
    int n  = blockIdx.z;
    int o0 = blockIdx.y * 32;
    int p0 = blockIdx.x * 32;
    int tx = threadIdx.x, ty = threadIdx.y;
#pragma unroll
    for (int i = 0; i < 4; i++) {
        int pl = ty + i*8;
        int oo = o0 + tx;
        tile[pl][tx] = g_y[((size_t)n*NP + p0 + pl)*CC + oo] * g_scale[oo] + g_shift[oo];
    }
    __syncthreads();
#pragma unroll
    for (int i = 0; i < 4; i++) {
        int ol = ty + i*8;
        out[((size_t)(n*CC + o0 + ol))*NP + p0 + tx] = tile[tx][ol];
    }
}

// ---------------- launch ----------------
extern "C" void kernel_launch(void* const* d_in, const int* in_sizes, int n_in,
                              void* d_out, int out_size) {
    const float* x     = (const float*)d_in[0];
    const float* wcat  = (const float*)d_in[1];
    const float* wscl  = (const float*)d_in[2];
    const float* gamma = (const float*)d_in[3];
    const float* beta  = (const float*)d_in[4];
    float* out = (float*)d_out;

    cudaFuncSetAttribute(k_gemm, cudaFuncAttributeMaxDynamicSharedMemorySize, SM_TOTAL);

    k_zero_stats<<<2, 256>>>();
    {
        dim3 g(3, 96, NB*8), b(32, 8);
        k_pad_split<<<g, b>>>(x);
    }
    k_wsplit<<<(NOUT*CC)/256, 256>>>(wscl, wcat);
    {
        dim3 g(NP/128, NOUT/128, NB);
        k_gemm<<<g, 256, SM_TOTAL>>>();
    }
    k_guid<<<(NB*NP*5 + 255)/256, 256>>>();
    k_gather<<<(NB*NP)/8, 256>>>();
    k_finalize<<<1, 256>>>(gamma, beta);
    {
        dim3 g(NP/32, CC/32, NB), b(32, 8);
        k_norm<<<g, b>>>(out);
    }
}

// round 12
// speedup vs baseline: 2.0300x; 2.0300x over previous
#include <cuda_runtime.h>
#include <cuda_fp16.h>
#include <cstdint>

#define HH 96
#define WW 96
#define CC 256
#define NP (HH*WW)          // 9216 pixels per image
#define NB 2
#define HP 98
#define PADP (HP*HP)        // 9604 padded pixels
#define NOUT 2048           // GEMM N: 1536 (Z) + 432 (guidance taps) + 80 pad
#define NGUID 1536
#define NTOT 18432.0f

// ---------------- static scratch ----------------
__device__ __half g_A[(size_t)NB*PADP*CC];      // padded NHWC x, fp16 (ring never read)
__device__ __half g_B[(size_t)NOUT*CC];         // [W_t ; tap weights] fp16
__device__ __half g_Z[(size_t)NB*NP*NOUT];      // GEMM output, fp16
__device__ float g_w[(size_t)NB*NP*48];         // guidance -> softmax weights
__device__ float g_y[(size_t)NB*NP*CC];         // pre-BN output, NHWC
__device__ float g_stats[512];
__device__ float g_scale[CC];
__device__ float g_shift[CC];

// ================= helpers =================
__device__ __forceinline__ uint32_t smem_u32(const void* p) {
    uint32_t a;
    asm("{ .reg .u64 t; cvta.to.shared.u64 t, %1; cvt.u32.u64 %0, t; }" : "=r"(a) : "l"(p));
    return a;
}
#define SWZ128(o) ((o) ^ (((o) >> 3) & 0x70))

__device__ __forceinline__ void ldsm_x4(uint32_t& r0, uint32_t& r1, uint32_t& r2, uint32_t& r3,
                                        uint32_t addr) {
    asm volatile("ldmatrix.sync.aligned.m8n8.x4.shared.b16 {%0,%1,%2,%3}, [%4];"
                 : "=r"(r0), "=r"(r1), "=r"(r2), "=r"(r3) : "r"(addr));
}
__device__ __forceinline__ void mma16816(float* d, const uint32_t* a, const uint32_t* b) {
    asm volatile("mma.sync.aligned.m16n8k16.row.col.f32.f16.f16.f32 "
                 "{%0,%1,%2,%3}, {%4,%5,%6,%7}, {%8,%9}, {%0,%1,%2,%3};"
                 : "+f"(d[0]), "+f"(d[1]), "+f"(d[2]), "+f"(d[3])
                 : "r"(a[0]), "r"(a[1]), "r"(a[2]), "r"(a[3]), "r"(b[0]), "r"(b[1]));
}
__device__ __forceinline__ void cpasync16(uint32_t dst, const void* src) {
    asm volatile("cp.async.cg.shared.global [%0], [%1], 16;" :: "r"(dst), "l"(src));
}
#define CP_COMMIT() asm volatile("cp.async.commit_group;" ::: "memory")
#define CP_WAIT(n)  asm volatile("cp.async.wait_group %0;" :: "n"(n) : "memory")

// ---------------- zero stats ----------------
__global__ void k_zero_stats() {
    int t = blockIdx.x*256 + threadIdx.x;
    if (t < 512) g_stats[t] = 0.f;
}

// ---------------- NCHW -> padded NHWC fp16 ----------------
__global__ void k_pad_split(const float* __restrict__ x) {
    __shared__ float tile[32][33];
    int n  = blockIdx.z >> 3;
    int c0 = (blockIdx.z & 7) * 32;
    int y  = blockIdx.y;
    int x0 = blockIdx.x * 32;
    int tx = threadIdx.x, ty = threadIdx.y;
#pragma unroll
    for (int i = 0; i < 4; i++) {
        int c = c0 + ty + i*8;
        tile[ty + i*8][tx] = x[(((size_t)n*CC + c)*HH + y)*WW + x0 + tx];
    }
    __syncthreads();
#pragma unroll
    for (int i = 0; i < 4; i++) {
        int xl = ty + i*8;
        int c  = c0 + tx;
        size_t idx = ((size_t)n*PADP + (size_t)(y+1)*HP + (x0 + xl + 1))*CC + c;
        g_A[idx] = __float2half(tile[tx][xl]);
    }
}

// ---------------- build B = [W_t ; tap weights], fp16 ----------------
__global__ void k_wsplit(const float* __restrict__ ws, const float* __restrict__ wcat) {
    int i = blockIdx.x*256 + threadIdx.x;   // over NOUT*CC
    int mp = i >> 8, c = i & 255;
    float v = 0.f;
    if (mp < NGUID) {
        int o = mp & 255, j = mp >> 8;
        v = ws[(size_t)o*NGUID + j*256 + c];
    } else if (mp < NGUID + 432) {
        int t = mp - NGUID, tap = t / 48, oc = t % 48;
        if (oc < 45) v = wcat[((size_t)(oc*256 + c))*9 + tap];
    }
    g_B[i] = __float2half(v);
}

// ---------------- warp-MMA GEMM, cp.async double-buffered, single fp16 ----------------
// Stage (32 KB): A 16K | B 16K. Two stages = 64 KB. 2 CTAs/SM (regs 128, no spill).
#define SM_A   0
#define SM_B   16384
#define STAGE_SZ 32768
#define SM_TOTAL (2*STAGE_SZ)

__global__ __launch_bounds__(256, 2) void k_gemm() {
    extern __shared__ char smem[];
    uint32_t smemu = smem_u32(smem);
    int tid = threadIdx.x, wid = tid >> 5, lane = tid & 31;
    int n  = blockIdx.z;
    int pb = blockIdx.x * 128;
    int nb = blockIdx.y * 128;

    // ---- loader mapping: thread -> (row r, half); 4x16B per array per chunk ----
    int r = tid >> 1;
    int half_ = tid & 1;
    int p  = pb + r;
    int py = p / WW, px = p % WW;
    size_t aoff = ((size_t)n*PADP + (size_t)(py+1)*HP + (px+1))*CC + half_*32;
    size_t boff = (size_t)(nb + r)*CC + half_*32;
    uint32_t so[4];
#pragma unroll
    for (int i = 0; i < 4; i++) {
        uint32_t o = (uint32_t)(r*128 + half_*64 + i*16);
        so[i] = SWZ128(o);
    }

    // ---- warp tile mapping: 4 warps over M (32 each), 2 over N (64 each) ----
    int wm = wid & 3, wn = wid >> 2;

    uint32_t xorv = (uint32_t)((lane & 7) << 4);
    int a_row0 = wm*32 + ((lane >> 3) & 1)*8 + (lane & 7);
    uint32_t a_colsel = (uint32_t)((lane >> 4) * 16);
    int b_row0 = wn*64 + ((lane >> 4))*8 + (lane & 7);
    uint32_t b_colsel = (uint32_t)(((lane >> 3) & 1) * 16);

    uint32_t aB0 = smemu + SM_A + (uint32_t)(a_row0*128);
    uint32_t aB1 = aB0 + 16*128;
    uint32_t bB  = smemu + SM_B + (uint32_t)(b_row0*128);

    float acc[2][8][4];
#pragma unroll
    for (int t = 0; t < 2; t++)
#pragma unroll
        for (int q = 0; q < 8; q++)
#pragma unroll
            for (int e = 0; e < 4; e++) acc[t][q][e] = 0.f;

    auto issue = [&](int kc, int stage) {
        uint32_t sb = smemu + (uint32_t)stage*STAGE_SZ;
        const uint4* pa  = (const uint4*)(g_A + aoff + kc*64);
        const uint4* pb_ = (const uint4*)(g_B + boff + kc*64);
#pragma unroll
        for (int i = 0; i < 4; i++) {
            cpasync16(sb + SM_A + so[i], pa  + i);
            cpasync16(sb + SM_B + so[i], pb_ + i);
        }
    };

    issue(0, 0);
    CP_COMMIT();

    for (int kc = 0; kc < 4; kc++) {
        if (kc < 3) {
            issue(kc + 1, (kc + 1) & 1);
            CP_COMMIT();
            CP_WAIT(1);
        } else {
            CP_WAIT(0);
        }
        __syncthreads();

        uint32_t soff = (uint32_t)(kc & 1) * STAGE_SZ;
#pragma unroll
        for (int ks = 0; ks < 4; ks++) {
            uint32_t aoffs = ((uint32_t)(ks*32) + a_colsel) ^ xorv;
            uint32_t boffs = ((uint32_t)(ks*32) + b_colsel) ^ xorv;

            uint32_t ah[2][4];
            ldsm_x4(ah[0][0], ah[0][1], ah[0][2], ah[0][3], aB0 + soff + aoffs);
            ldsm_x4(ah[1][0], ah[1][1], ah[1][2], ah[1][3], aB1 + soff + aoffs);

#pragma unroll
            for (int qp = 0; qp < 4; qp++) {
                uint32_t bh[4];
                ldsm_x4(bh[0], bh[1], bh[2], bh[3], bB + soff + (uint32_t)(qp*16*128) + boffs);
                int q0 = qp*2, q1 = qp*2 + 1;
                mma16816(acc[0][q0], ah[0], bh + 0);
                mma16816(acc[1][q0], ah[1], bh + 0);
                mma16816(acc[0][q1], ah[0], bh + 2);
                mma16816(acc[1][q1], ah[1], bh + 2);
            }
        }
        __syncthreads();
    }

    // ---- epilogue: write fragments to g_Z as fp16 ----
#pragma unroll
    for (int t = 0; t < 2; t++) {
        size_t row = (size_t)n*NP + pb + wm*32 + t*16 + (lane >> 2);
        __half* zbase = g_Z + row*NOUT + nb + wn*64 + (lane & 3)*2;
#pragma unroll
        for (int q = 0; q < 8; q++) {
            *(__half2*)(zbase + q*8)          = __floats2half2_rn(acc[t][q][0], acc[t][q][1]);
            *(__half2*)(zbase + q*8 + 8*NOUT) = __floats2half2_rn(acc[t][q][2], acc[t][q][3]);
        }
    }
}

// ---------------- guidance = shifted sum of tap partials ----------------
__global__ void k_gsum() {
    int i = blockIdx.x*256 + threadIdx.x;
    if (i >= NB*NP*48) return;
    int oc = i % 48;
    int P  = i / 48;
    int n  = P / NP, p = P % NP;
    int py = p / WW, px = p % WW;
    float s = 0.f;
#pragma unroll
    for (int tap = 0; tap < 9; tap++) {
        int dy = tap/3 - 1, dx = tap%3 - 1;
        int qy = py + dy, qx = px + dx;
        if ((unsigned)qy < HH && (unsigned)qx < WW)
            s += __half2float(g_Z[((size_t)n*NP + qy*WW + qx)*NOUT + NGUID + tap*48 + oc]);
    }
    g_w[(size_t)P*48 + oc] = s;
}

// ---------------- softmax over each 9-channel group ----------------
__global__ void k_softmax() {
    int i = blockIdx.x*256 + threadIdx.x;
    if (i >= NB*NP*5) return;
    int br  = i % 5;
    int np_ = i / 5;
    float* row = g_w + (size_t)np_*48 + 9*br;
    float v[9], m = -1e30f;
#pragma unroll
    for (int k = 0; k < 9; k++) { v[k] = row[k]; m = fmaxf(m, v[k]); }
    float s = 0.f;
#pragma unroll
    for (int k = 0; k < 9; k++) { v[k] = __expf(v[k] - m); s += v[k]; }
    float inv = 1.f / s;
#pragma unroll
    for (int k = 0; k < 9; k++) row[k] = v[k] * inv;
}

// ---------------- gather + fused BN-stats ----------------
__device__ __forceinline__ void h8_fma(float* A, uint4 raw, float w) {
    __half2* h = (__half2*)&raw;
#pragma unroll
    for (int j = 0; j < 4; j++) {
        float2 f = __half22float2(h[j]);
        A[j*2+0] += w * f.x;
        A[j*2+1] += w * f.y;
    }
}

__global__ __launch_bounds__(256) void k_gather() {
    __shared__ float wsh[8][48];
    __shared__ float ssum[256], ssq[256];
    int tid = threadIdx.x;
    int warp = tid >> 5, lane = tid & 31;
    ssum[tid] = 0.f; ssq[tid] = 0.f;

    int P = blockIdx.x*8 + warp;
    int n = P / NP, p = P % NP;
    int py = p / WW, px = p % WW;

    const float* wrow = g_w + (size_t)P*48;
    if (lane < 45) wsh[warp][lane] = wrow[lane];
    if (lane < 13) wsh[warp][32 + lane] = wrow[32 + lane];
    __syncthreads();

    float A[8];
    {
        uint4 raw = *(const uint4*)(g_Z + (size_t)P*NOUT + lane*8);
        __half2* h = (__half2*)&raw;
#pragma unroll
        for (int j = 0; j < 4; j++) {
            float2 f = __half22float2(h[j]);
            A[j*2+0] = f.x;
            A[j*2+1] = f.y;
        }
    }

    const int DS[5] = {1, 6, 12, 24, 36};
#pragma unroll
    for (int br = 0; br < 5; ++br) {
        int d = DS[br];
#pragma unroll
        for (int k = 0; k < 9; k++) {
            int dy = (k/3 - 1)*d, dx = (k%3 - 1)*d;
            int ny = py + dy, nx = px + dx;
            if ((unsigned)ny < HH && (unsigned)nx < WW) {
                float w = wsh[warp][br*9 + k];
                uint4 raw = *(const uint4*)(g_Z + ((size_t)n*NP + ny*WW + nx)*NOUT + (br+1)*256 + lane*8);
                h8_fma(A, raw, w);
            }
        }
    }

    float* yr = g_y + (size_t)P*CC + lane*8;
#pragma unroll
    for (int j = 0; j < 8; j++) yr[j] = A[j];

    // fused BN stats: smem accumulate then one global atomic per channel
#pragma unroll
    for (int j = 0; j < 8; j++) {
        atomicAdd(&ssum[lane*8 + j], A[j]);
        atomicAdd(&ssq[lane*8 + j], A[j]*A[j]);
    }
    __syncthreads();
    if (warp < 4) {
        int c = tid;
        atomicAdd(&g_stats[c], ssum[c]);
        atomicAdd(&g_stats[256 + c], ssq[c]);
        c = tid + 128;
        atomicAdd(&g_stats[c], ssum[c]);
        atomicAdd(&g_stats[256 + c], ssq[c]);
    }
}

__global__ void k_finalize(const float* __restrict__ gamma, const float* __restrict__ beta) {
    int t = threadIdx.x;
    float mean = g_stats[t] / NTOT;
    float var  = g_stats[256 + t] / NTOT - mean*mean;
    float rstd = rsqrtf(var + 1e-5f);
    float sc = gamma[t] * rstd;
    g_scale[t] = sc;
    g_shift[t] = beta[t] - mean*sc;
}

// ---------------- affine + NHWC -> NCHW ----------------
__global__ void k_norm(float* __restrict__ out) {
    __shared__ float tile[32][33];
    int n  = blockIdx.z;
    int o0 = blockIdx.y * 32;
    int p0 = blockIdx.x * 32;
    int tx = threadIdx.x, ty = threadIdx.y;
#pragma unroll
    for (int i = 0; i < 4; i++) {
        int pl = ty + i*8;
        int oo = o0 + tx;
        tile[pl][tx] = g_y[((size_t)n*NP + p0 + pl)*CC + oo] * g_scale[oo] + g_shift[oo];
    }
    __syncthreads();
#pragma unroll
    for (int i = 0; i < 4; i++) {
        int ol = ty + i*8;
        out[((size_t)(n*CC + o0 + ol))*NP + p0 + tx] = tile[tx][ol];
    }
}

// ---------------- launch ----------------
extern "C" void kernel_launch(void* const* d_in, const int* in_sizes, int n_in,
                              void* d_out, int out_size) {
    const float* x     = (const float*)d_in[0];
    const float* wcat  = (const float*)d_in[1];
    const float* wscl  = (const float*)d_in[2];
    const float* gamma = (const float*)d_in[3];
    const float* beta  = (const float*)d_in[4];
    float* out = (float*)d_out;

    cudaFuncSetAttribute(k_gemm, cudaFuncAttributeMaxDynamicSharedMemorySize, SM_TOTAL);

    k_zero_stats<<<2, 256>>>();
    {
        dim3 g(3, 96, NB*8), b(32, 8);
        k_pad_split<<<g, b>>>(x);
    }
    k_wsplit<<<(NOUT*CC)/256, 256>>>(wscl, wcat);
    {
        dim3 g(NP/128, NOUT/128, NB);
        k_gemm<<<g, 256, SM_TOTAL>>>();
    }
    k_gsum<<<(NB*NP*48 + 255)/256, 256>>>();
    k_softmax<<<(NB*NP*5 + 255)/256, 256>>>();
    k_gather<<<(NB*NP)/8, 256>>>();
    k_finalize<<<1, 256>>>(gamma, beta);
    {
        dim3 g(NP/32, CC/32, NB), b(32, 8);
        k_norm<<<g, b>>>(out);
    }
}

// round 14
// speedup vs baseline: 2.1804x; 1.0741x over previous
#include <cuda_runtime.h>
#include <cuda_fp16.h>
#include <cstdint>

#define HH 96
#define WW 96
#define CC 256
#define NP (HH*WW)          // 9216 pixels per image
#define NB 2
#define HP 98
#define PADP (HP*HP)        // 9604 padded pixels
#define NOUT 2048           // GEMM N: 1536 (Z) + 432 (guidance taps) + 80 pad
#define NGUID 1536
#define NTOT 18432.0f

// ---------------- static scratch ----------------
__device__ __half g_A[(size_t)NB*PADP*CC];      // padded NHWC x, fp16 (ring never read)
__device__ __half g_B[(size_t)NOUT*CC];         // [W_t ; tap weights] fp16
__device__ __half g_Z[(size_t)NB*NP*NOUT];      // GEMM output, fp16
__device__ __half g_yh[(size_t)NB*NP*CC];       // pre-BN output, NHWC, fp16
__device__ float g_stats[512];
__device__ float g_scale[CC];
__device__ float g_shift[CC];

// ================= helpers =================
__device__ __forceinline__ uint32_t smem_u32(const void* p) {
    uint32_t a;
    asm("{ .reg .u64 t; cvta.to.shared.u64 t, %1; cvt.u32.u64 %0, t; }" : "=r"(a) : "l"(p));
    return a;
}
#define SWZ128(o) ((o) ^ (((o) >> 3) & 0x70))

__device__ __forceinline__ void ldsm_x4(uint32_t& r0, uint32_t& r1, uint32_t& r2, uint32_t& r3,
                                        uint32_t addr) {
    asm volatile("ldmatrix.sync.aligned.m8n8.x4.shared.b16 {%0,%1,%2,%3}, [%4];"
                 : "=r"(r0), "=r"(r1), "=r"(r2), "=r"(r3) : "r"(addr));
}
__device__ __forceinline__ void mma16816(float* d, const uint32_t* a, const uint32_t* b) {
    asm volatile("mma.sync.aligned.m16n8k16.row.col.f32.f16.f16.f32 "
                 "{%0,%1,%2,%3}, {%4,%5,%6,%7}, {%8,%9}, {%0,%1,%2,%3};"
                 : "+f"(d[0]), "+f"(d[1]), "+f"(d[2]), "+f"(d[3])
                 : "r"(a[0]), "r"(a[1]), "r"(a[2]), "r"(a[3]), "r"(b[0]), "r"(b[1]));
}
__device__ __forceinline__ void cpasync16(uint32_t dst, const void* src) {
    asm volatile("cp.async.cg.shared.global [%0], [%1], 16;" :: "r"(dst), "l"(src));
}
#define CP_COMMIT() asm volatile("cp.async.commit_group;" ::: "memory")
#define CP_WAIT(n)  asm volatile("cp.async.wait_group %0;" :: "n"(n) : "memory")

// ---------------- NCHW -> padded NHWC fp16 ----------------
__global__ void k_pad_split(const float* __restrict__ x) {
    __shared__ float tile[32][33];
    int n  = blockIdx.z >> 3;
    int c0 = (blockIdx.z & 7) * 32;
    int y  = blockIdx.y;
    int x0 = blockIdx.x * 32;
    int tx = threadIdx.x, ty = threadIdx.y;
#pragma unroll
    for (int i = 0; i < 4; i++) {
        int c = c0 + ty + i*8;
        tile[ty + i*8][tx] = x[(((size_t)n*CC + c)*HH + y)*WW + x0 + tx];
    }
    __syncthreads();
#pragma unroll
    for (int i = 0; i < 4; i++) {
        int xl = ty + i*8;
        int c  = c0 + tx;
        size_t idx = ((size_t)n*PADP + (size_t)(y+1)*HP + (x0 + xl + 1))*CC + c;
        g_A[idx] = __float2half(tile[tx][xl]);
    }
}

// ---------------- build B = [W_t ; tap weights] fp16; block 0 zeroes stats ----------------
__global__ void k_wsplit(const float* __restrict__ ws, const float* __restrict__ wcat) {
    int i = blockIdx.x*256 + threadIdx.x;   // over NOUT*CC
    if (blockIdx.x == 0) {
        g_stats[threadIdx.x] = 0.f;
        g_stats[256 + threadIdx.x] = 0.f;
    }
    int mp = i >> 8, c = i & 255;
    float v = 0.f;
    if (mp < NGUID) {
        int o = mp & 255, j = mp >> 8;
        v = ws[(size_t)o*NGUID + j*256 + c];
    } else if (mp < NGUID + 432) {
        int t = mp - NGUID, tap = t / 48, oc = t % 48;
        if (oc < 45) v = wcat[((size_t)(oc*256 + c))*9 + tap];
    }
    g_B[i] = __float2half(v);
}

// ---------------- warp-MMA GEMM, cp.async double-buffered, single fp16 ----------------
// Stage (32 KB): A 16K | B 16K. Two stages = 64 KB. 2 CTAs/SM (regs 128, no spill).
#define SM_A   0
#define SM_B   16384
#define STAGE_SZ 32768
#define SM_TOTAL (2*STAGE_SZ)

__global__ __launch_bounds__(256, 2) void k_gemm() {
    extern __shared__ char smem[];
    uint32_t smemu = smem_u32(smem);
    int tid = threadIdx.x, wid = tid >> 5, lane = tid & 31;
    int n  = blockIdx.z;
    int pb = blockIdx.x * 128;
    int nb = blockIdx.y * 128;

    // ---- loader mapping: thread -> (row r, half); 4x16B per array per chunk ----
    int r = tid >> 1;
    int half_ = tid & 1;
    int p  = pb + r;
    int py = p / WW, px = p % WW;
    size_t aoff = ((size_t)n*PADP + (size_t)(py+1)*HP + (px+1))*CC + half_*32;
    size_t boff = (size_t)(nb + r)*CC + half_*32;
    uint32_t so[4];
#pragma unroll
    for (int i = 0; i < 4; i++) {
        uint32_t o = (uint32_t)(r*128 + half_*64 + i*16);
        so[i] = SWZ128(o);
    }

    // ---- warp tile mapping: 4 warps over M (32 each), 2 over N (64 each) ----
    int wm = wid & 3, wn = wid >> 2;

    uint32_t xorv = (uint32_t)((lane & 7) << 4);
    int a_row0 = wm*32 + ((lane >> 3) & 1)*8 + (lane & 7);
    uint32_t a_colsel = (uint32_t)((lane >> 4) * 16);
    int b_row0 = wn*64 + ((lane >> 4))*8 + (lane & 7);
    uint32_t b_colsel = (uint32_t)(((lane >> 3) & 1) * 16);

    uint32_t aB0 = smemu + SM_A + (uint32_t)(a_row0*128);
    uint32_t aB1 = aB0 + 16*128;
    uint32_t bB  = smemu + SM_B + (uint32_t)(b_row0*128);

    float acc[2][8][4];
#pragma unroll
    for (int t = 0; t < 2; t++)
#pragma unroll
        for (int q = 0; q < 8; q++)
#pragma unroll
            for (int e = 0; e < 4; e++) acc[t][q][e] = 0.f;

    auto issue = [&](int kc, int stage) {
        uint32_t sb = smemu + (uint32_t)stage*STAGE_SZ;
        const uint4* pa  = (const uint4*)(g_A + aoff + kc*64);
        const uint4* pb_ = (const uint4*)(g_B + boff + kc*64);
#pragma unroll
        for (int i = 0; i < 4; i++) {
            cpasync16(sb + SM_A + so[i], pa  + i);
            cpasync16(sb + SM_B + so[i], pb_ + i);
        }
    };

    issue(0, 0);
    CP_COMMIT();

    for (int kc = 0; kc < 4; kc++) {
        if (kc < 3) {
            issue(kc + 1, (kc + 1) & 1);
            CP_COMMIT();
            CP_WAIT(1);
        } else {
            CP_WAIT(0);
        }
        __syncthreads();

        uint32_t soff = (uint32_t)(kc & 1) * STAGE_SZ;
#pragma unroll
        for (int ks = 0; ks < 4; ks++) {
            uint32_t aoffs = ((uint32_t)(ks*32) + a_colsel) ^ xorv;
            uint32_t boffs = ((uint32_t)(ks*32) + b_colsel) ^ xorv;

            uint32_t ah[2][4];
            ldsm_x4(ah[0][0], ah[0][1], ah[0][2], ah[0][3], aB0 + soff + aoffs);
            ldsm_x4(ah[1][0], ah[1][1], ah[1][2], ah[1][3], aB1 + soff + aoffs);

#pragma unroll
            for (int qp = 0; qp < 4; qp++) {
                uint32_t bh[4];
                ldsm_x4(bh[0], bh[1], bh[2], bh[3], bB + soff + (uint32_t)(qp*16*128) + boffs);
                int q0 = qp*2, q1 = qp*2 + 1;
                mma16816(acc[0][q0], ah[0], bh + 0);
                mma16816(acc[1][q0], ah[1], bh + 0);
                mma16816(acc[0][q1], ah[0], bh + 2);
                mma16816(acc[1][q1], ah[1], bh + 2);
            }
        }
        __syncthreads();
    }

    // ---- epilogue: write fragments to g_Z as fp16 ----
#pragma unroll
    for (int t = 0; t < 2; t++) {
        size_t row = (size_t)n*NP + pb + wm*32 + t*16 + (lane >> 2);
        __half* zbase = g_Z + row*NOUT + nb + wn*64 + (lane & 3)*2;
#pragma unroll
        for (int q = 0; q < 8; q++) {
            *(__half2*)(zbase + q*8)          = __floats2half2_rn(acc[t][q][0], acc[t][q][1]);
            *(__half2*)(zbase + q*8 + 8*NOUT) = __floats2half2_rn(acc[t][q][2], acc[t][q][3]);
        }
    }
}

// ---------------- fused guidance(sum+softmax) + gather + BN-stats ----------------
__device__ __forceinline__ void h8_fma(float* A, uint4 raw, float w) {
    __half2* h = (__half2*)&raw;
#pragma unroll
    for (int j = 0; j < 4; j++) {
        float2 f = __half22float2(h[j]);
        A[j*2+0] += w * f.x;
        A[j*2+1] += w * f.y;
    }
}

__global__ __launch_bounds__(256) void k_gather() {
    __shared__ float wsh[8][48];
    __shared__ float ssum[256], ssq[256];
    int tid = threadIdx.x;
    int warp = tid >> 5, lane = tid & 31;
    ssum[tid] = 0.f; ssq[tid] = 0.f;

    int P = blockIdx.x*8 + warp;
    int n = P / NP, p = P % NP;
    int py = p / WW, px = p % WW;

    // ---- phase 1: guidance shifted-sum (per-warp, lanes cover 45 channels) ----
    {
        float s0 = 0.f, s1 = 0.f;          // channel lane, channel 32+lane
#pragma unroll
        for (int tap = 0; tap < 9; tap++) {
            int dy = tap/3 - 1, dx = tap%3 - 1;
            int qy = py + dy, qx = px + dx;
            if ((unsigned)qy < HH && (unsigned)qx < WW) {
                const __half* zr = g_Z + ((size_t)n*NP + qy*WW + qx)*NOUT + NGUID + tap*48;
                s0 += __half2float(zr[lane]);
                if (lane < 13) s1 += __half2float(zr[32 + lane]);
            }
        }
        wsh[warp][lane] = s0;
        if (lane < 13) wsh[warp][32 + lane] = s1;
    }
    __syncwarp();
    // ---- phase 2: softmax per branch (lanes 0-4) ----
    if (lane < 5) {
        float v[9], m = -1e30f;
#pragma unroll
        for (int k = 0; k < 9; k++) { v[k] = wsh[warp][lane*9 + k]; m = fmaxf(m, v[k]); }
        float s = 0.f;
#pragma unroll
        for (int k = 0; k < 9; k++) { v[k] = __expf(v[k] - m); s += v[k]; }
        float inv = 1.f / s;
#pragma unroll
        for (int k = 0; k < 9; k++) wsh[warp][lane*9 + k] = v[k] * inv;
    }
    __syncthreads();   // also covers ssum/ssq init

    // ---- phase 3: gather ----
    float A[8];
    {
        uint4 raw = *(const uint4*)(g_Z + (size_t)P*NOUT + lane*8);
        __half2* h = (__half2*)&raw;
#pragma unroll
        for (int j = 0; j < 4; j++) {
            float2 f = __half22float2(h[j]);
            A[j*2+0] = f.x;
            A[j*2+1] = f.y;
        }
    }

    const int DS[5] = {1, 6, 12, 24, 36};
#pragma unroll
    for (int br = 0; br < 5; ++br) {
        int d = DS[br];
#pragma unroll
        for (int k = 0; k < 9; k++) {
            int dy = (k/3 - 1)*d, dx = (k%3 - 1)*d;
            int ny = py + dy, nx = px + dx;
            if ((unsigned)ny < HH && (unsigned)nx < WW) {
                float w = wsh[warp][br*9 + k];
                uint4 raw = *(const uint4*)(g_Z + ((size_t)n*NP + ny*WW + nx)*NOUT + (br+1)*256 + lane*8);
                h8_fma(A, raw, w);
            }
        }
    }

    // store y as fp16
    {
        __half* yr = g_yh + (size_t)P*CC + lane*8;
        uint4 packed;
        __half2* hp = (__half2*)&packed;
#pragma unroll
        for (int j = 0; j < 4; j++) hp[j] = __floats2half2_rn(A[j*2+0], A[j*2+1]);
        *(uint4*)yr = packed;
    }

    // fused BN stats: smem accumulate then one global atomic per channel
#pragma unroll
    for (int j = 0; j < 8; j++) {
        atomicAdd(&ssum[lane*8 + j], A[j]);
        atomicAdd(&ssq[lane*8 + j], A[j]*A[j]);
    }
    __syncthreads();
    if (warp < 4) {
        int c = tid;
        atomicAdd(&g_stats[c], ssum[c]);
        atomicAdd(&g_stats[256 + c], ssq[c]);
        c = tid + 128;
        atomicAdd(&g_stats[c], ssum[c]);
        atomicAdd(&g_stats[256 + c], ssq[c]);
    }
}

__global__ void k_finalize(const float* __restrict__ gamma, const float* __restrict__ beta) {
    int t = threadIdx.x;
    float mean = g_stats[t] / NTOT;
    float var  = g_stats[256 + t] / NTOT - mean*mean;
    float rstd = rsqrtf(var + 1e-5f);
    float sc = gamma[t] * rstd;
    g_scale[t] = sc;
    g_shift[t] = beta[t] - mean*sc;
}

// ---------------- affine + NHWC(fp16) -> NCHW(fp32) ----------------
__global__ void k_norm(float* __restrict__ out) {
    __shared__ float tile[32][33];
    int n  = blockIdx.z;
    int o0 = blockIdx.y * 32;
    int p0 = blockIdx.x * 32;
    int tx = threadIdx.x, ty = threadIdx.y;
#pragma unroll
    for (int i = 0; i < 4; i++) {
        int pl = ty + i*8;
        int oo = o0 + tx;
        float v = __half2float(g_yh[((size_t)n*NP + p0 + pl)*CC + oo]);
        tile[pl][tx] = v * g_scale[oo] + g_shift[oo];
    }
    __syncthreads();
#pragma unroll
    for (int i = 0; i < 4; i++) {
        int ol = ty + i*8;
        out[((size_t)(n*CC + o0 + ol))*NP + p0 + tx] = tile[tx][ol];
    }
}

// ---------------- launch ----------------
extern "C" void kernel_launch(void* const* d_in, const int* in_sizes, int n_in,
                              void* d_out, int out_size) {
    const float* x     = (const float*)d_in[0];
    const float* wcat  = (const float*)d_in[1];
    const float* wscl  = (const float*)d_in[2];
    const float* gamma = (const float*)d_in[3];
    const float* beta  = (const float*)d_in[4];
    float* out = (float*)d_out;

    cudaFuncSetAttribute(k_gemm, cudaFuncAttributeMaxDynamicSharedMemorySize, SM_TOTAL);

    {
        dim3 g(3, 96, NB*8), b(32, 8);
        k_pad_split<<<g, b>>>(x);
    }
    k_wsplit<<<(NOUT*CC)/256, 256>>>(wscl, wcat);
    {
        dim3 g(NP/128, NOUT/128, NB);
        k_gemm<<<g, 256, SM_TOTAL>>>();
    }
    k_gather<<<(NB*NP)/8, 256>>>();
    k_finalize<<<1, 256>>>(gamma, beta);
    {
        dim3 g(NP/32, CC/32, NB), b(32, 8);
        k_norm<<<g, b>>>(out);
    }
}

// round 17
// speedup vs baseline: 2.3997x; 1.1006x over previous
#include <cuda_runtime.h>
#include <cuda_fp16.h>
#include <cstdint>

#define HH 96
#define WW 96
#define CC 256
#define NP (HH*WW)          // 9216 pixels per image
#define NB 2
#define HP 98
#define PADP (HP*HP)        // 9604 padded pixels
#define NOUT 2048           // GEMM N: 1536 (Z) + 432 (guidance taps) + 80 pad
#define NGUID 1536
#define NTOT 18432.0f

// ---------------- static scratch ----------------
__device__ __half g_A[(size_t)NB*PADP*CC];      // padded NHWC x, fp16 (ring never read)
__device__ __half g_B[(size_t)NOUT*CC];         // [W_t ; tap weights] fp16
__device__ __half g_Z[(size_t)NB*NP*NOUT];      // GEMM output, fp16
__device__ __half g_yh[(size_t)NB*NP*CC];       // pre-BN output, NHWC, fp16
__device__ float g_stats[512];

// ================= helpers =================
__device__ __forceinline__ uint32_t smem_u32(const void* p) {
    uint32_t a;
    asm("{ .reg .u64 t; cvta.to.shared.u64 t, %1; cvt.u32.u64 %0, t; }" : "=r"(a) : "l"(p));
    return a;
}
#define SWZ128(o) ((o) ^ (((o) >> 3) & 0x70))

__device__ __forceinline__ void ldsm_x4(uint32_t& r0, uint32_t& r1, uint32_t& r2, uint32_t& r3,
                                        uint32_t addr) {
    asm volatile("ldmatrix.sync.aligned.m8n8.x4.shared.b16 {%0,%1,%2,%3}, [%4];"
                 : "=r"(r0), "=r"(r1), "=r"(r2), "=r"(r3) : "r"(addr));
}
__device__ __forceinline__ void mma16816(float* d, const uint32_t* a, const uint32_t* b) {
    asm volatile("mma.sync.aligned.m16n8k16.row.col.f32.f16.f16.f32 "
                 "{%0,%1,%2,%3}, {%4,%5,%6,%7}, {%8,%9}, {%0,%1,%2,%3};"
                 : "+f"(d[0]), "+f"(d[1]), "+f"(d[2]), "+f"(d[3])
                 : "r"(a[0]), "r"(a[1]), "r"(a[2]), "r"(a[3]), "r"(b[0]), "r"(b[1]));
}
__device__ __forceinline__ void cpasync16(uint32_t dst, const void* src) {
    asm volatile("cp.async.cg.shared.global [%0], [%1], 16;" :: "r"(dst), "l"(src));
}
#define CP_COMMIT() asm volatile("cp.async.commit_group;" ::: "memory")
#define CP_WAIT(n)  asm volatile("cp.async.wait_group %0;" :: "n"(n) : "memory")

// ---------------- NCHW -> padded NHWC fp16 ----------------
__global__ void k_pad_split(const float* __restrict__ x) {
    __shared__ float tile[32][33];
    int n  = blockIdx.z >> 3;
    int c0 = (blockIdx.z & 7) * 32;
    int y  = blockIdx.y;
    int x0 = blockIdx.x * 32;
    int tx = threadIdx.x, ty = threadIdx.y;
#pragma unroll
    for (int i = 0; i < 4; i++) {
        int c = c0 + ty + i*8;
        tile[ty + i*8][tx] = x[(((size_t)n*CC + c)*HH + y)*WW + x0 + tx];
    }
    __syncthreads();
#pragma unroll
    for (int i = 0; i < 4; i++) {
        int xl = ty + i*8;
        int c  = c0 + tx;
        size_t idx = ((size_t)n*PADP + (size_t)(y+1)*HP + (x0 + xl + 1))*CC + c;
        g_A[idx] = __float2half(tile[tx][xl]);
    }
}

// ---------------- build B = [W_t ; tap weights] fp16; block 0 zeroes stats ----------------
__global__ void k_wsplit(const float* __restrict__ ws, const float* __restrict__ wcat) {
    int i = blockIdx.x*256 + threadIdx.x;   // over NOUT*CC
    if (blockIdx.x == 0) {
        g_stats[threadIdx.x] = 0.f;
        g_stats[256 + threadIdx.x] = 0.f;
    }
    int mp = i >> 8, c = i & 255;
    float v = 0.f;
    if (mp < NGUID) {
        int o = mp & 255, j = mp >> 8;
        v = ws[(size_t)o*NGUID + j*256 + c];
    } else if (mp < NGUID + 432) {
        int t = mp - NGUID, tap = t / 48, oc = t % 48;
        if (oc < 45) v = wcat[((size_t)(oc*256 + c))*9 + tap];
    }
    g_B[i] = __float2half(v);
}

// ---------------- warp-MMA GEMM, cp.async 3-stage pipeline, single fp16 ----------------
// Stage (32 KB): A 16K | B 16K. Three stages = 96 KB. 2 CTAs/SM (regs 128, no spill).
#define SM_A   0
#define SM_B   16384
#define STAGE_SZ 32768
#define SM_TOTAL (3*STAGE_SZ)

__global__ __launch_bounds__(256, 2) void k_gemm() {
    extern __shared__ char smem[];
    uint32_t smemu = smem_u32(smem);
    int tid = threadIdx.x, wid = tid >> 5, lane = tid & 31;
    int n  = blockIdx.z;
    int pb = blockIdx.x * 128;
    int nb = blockIdx.y * 128;

    // ---- loader mapping: thread -> (row r, half); 4x16B per array per chunk ----
    int r = tid >> 1;
    int half_ = tid & 1;
    int p  = pb + r;
    int py = p / WW, px = p % WW;
    size_t aoff = ((size_t)n*PADP + (size_t)(py+1)*HP + (px+1))*CC + half_*32;
    size_t boff = (size_t)(nb + r)*CC + half_*32;
    uint32_t so[4];
#pragma unroll
    for (int i = 0; i < 4; i++) {
        uint32_t o = (uint32_t)(r*128 + half_*64 + i*16);
        so[i] = SWZ128(o);
    }

    // ---- warp tile mapping: 4 warps over M (32 each), 2 over N (64 each) ----
    int wm = wid & 3, wn = wid >> 2;

    uint32_t xorv = (uint32_t)((lane & 7) << 4);
    int a_row0 = wm*32 + ((lane >> 3) & 1)*8 + (lane & 7);
    uint32_t a_colsel = (uint32_t)((lane >> 4) * 16);
    int b_row0 = wn*64 + ((lane >> 4))*8 + (lane & 7);
    uint32_t b_colsel = (uint32_t)(((lane >> 3) & 1) * 16);

    uint32_t aB0 = smemu + SM_A + (uint32_t)(a_row0*128);
    uint32_t aB1 = aB0 + 16*128;
    uint32_t bB  = smemu + SM_B + (uint32_t)(b_row0*128);

    float acc[2][8][4];
#pragma unroll
    for (int t = 0; t < 2; t++)
#pragma unroll
        for (int q = 0; q < 8; q++)
#pragma unroll
            for (int e = 0; e < 4; e++) acc[t][q][e] = 0.f;

    auto issue = [&](int kc, int stage) {
        uint32_t sb = smemu + (uint32_t)stage*STAGE_SZ;
        const uint4* pa  = (const uint4*)(g_A + aoff + kc*64);
        const uint4* pb_ = (const uint4*)(g_B + boff + kc*64);
#pragma unroll
        for (int i = 0; i < 4; i++) {
            cpasync16(sb + SM_A + so[i], pa  + i);
            cpasync16(sb + SM_B + so[i], pb_ + i);
        }
    };

    issue(0, 0);
    CP_COMMIT();
    issue(1, 1);
    CP_COMMIT();

    for (int kc = 0; kc < 4; kc++) {
        if (kc < 2) {
            issue(kc + 2, (kc + 2) % 3);
            CP_COMMIT();
            CP_WAIT(2);
        } else if (kc == 2) {
            CP_WAIT(1);
        } else {
            CP_WAIT(0);
        }
        __syncthreads();

        uint32_t soff = (uint32_t)(kc % 3) * STAGE_SZ;
#pragma unroll
        for (int ks = 0; ks < 4; ks++) {
            uint32_t aoffs = ((uint32_t)(ks*32) + a_colsel) ^ xorv;
            uint32_t boffs = ((uint32_t)(ks*32) + b_colsel) ^ xorv;

            uint32_t ah[2][4];
            ldsm_x4(ah[0][0], ah[0][1], ah[0][2], ah[0][3], aB0 + soff + aoffs);
            ldsm_x4(ah[1][0], ah[1][1], ah[1][2], ah[1][3], aB1 + soff + aoffs);

#pragma unroll
            for (int qp = 0; qp < 4; qp++) {
                uint32_t bh[4];
                ldsm_x4(bh[0], bh[1], bh[2], bh[3], bB + soff + (uint32_t)(qp*16*128) + boffs);
                int q0 = qp*2, q1 = qp*2 + 1;
                mma16816(acc[0][q0], ah[0], bh + 0);
                mma16816(acc[1][q0], ah[1], bh + 0);
                mma16816(acc[0][q1], ah[0], bh + 2);
                mma16816(acc[1][q1], ah[1], bh + 2);
            }
        }
        __syncthreads();
    }

    // ---- epilogue: write fragments to g_Z as fp16 ----
#pragma unroll
    for (int t = 0; t < 2; t++) {
        size_t row = (size_t)n*NP + pb + wm*32 + t*16 + (lane >> 2);
        __half* zbase = g_Z + row*NOUT + nb + wn*64 + (lane & 3)*2;
#pragma unroll
        for (int q = 0; q < 8; q++) {
            *(__half2*)(zbase + q*8)          = __floats2half2_rn(acc[t][q][0], acc[t][q][1]);
            *(__half2*)(zbase + q*8 + 8*NOUT) = __floats2half2_rn(acc[t][q][2], acc[t][q][3]);
        }
    }
}

// ---------------- fused guidance(sum+softmax) + gather + BN-stats ----------------
__device__ __forceinline__ void h8_fma(float* A, uint4 raw, float w) {
    __half2* h = (__half2*)&raw;
#pragma unroll
    for (int j = 0; j < 4; j++) {
        float2 f = __half22float2(h[j]);
        A[j*2+0] += w * f.x;
        A[j*2+1] += w * f.y;
    }
}

__global__ void k_gather() {
    __shared__ float wsh[8][48];
    __shared__ float ssum[256], ssq[256];
    int tid = threadIdx.x;
    int warp = tid >> 5, lane = tid & 31;
    ssum[tid] = 0.f; ssq[tid] = 0.f;

    int P = blockIdx.x*8 + warp;
    int n = P / NP, p = P % NP;
    int py = p / WW, px = p % WW;

    // ---- phase 1: guidance shifted-sum (per-warp, lanes cover 45 channels) ----
    {
        float s0 = 0.f, s1 = 0.f;
#pragma unroll
        for (int tap = 0; tap < 9; tap++) {
            int dy = tap/3 - 1, dx = tap%3 - 1;
            int qy = py + dy, qx = px + dx;
            if ((unsigned)qy < HH && (unsigned)qx < WW) {
                const __half* zr = g_Z + ((size_t)n*NP + qy*WW + qx)*NOUT + NGUID + tap*48;
                s0 += __half2float(zr[lane]);
                if (lane < 13) s1 += __half2float(zr[32 + lane]);
            }
        }
        wsh[warp][lane] = s0;
        if (lane < 13) wsh[warp][32 + lane] = s1;
    }
    __syncwarp();
    // ---- phase 2: softmax per branch (lanes 0-4) ----
    if (lane < 5) {
        float v[9], m = -1e30f;
#pragma unroll
        for (int k = 0; k < 9; k++) { v[k] = wsh[warp][lane*9 + k]; m = fmaxf(m, v[k]); }
        float s = 0.f;
#pragma unroll
        for (int k = 0; k < 9; k++) { v[k] = __expf(v[k] - m); s += v[k]; }
        float inv = 1.f / s;
#pragma unroll
        for (int k = 0; k < 9; k++) wsh[warp][lane*9 + k] = v[k] * inv;
    }
    __syncthreads();   // also covers ssum/ssq init

    // ---- phase 3: gather, 9-load register batches per branch (high MLP) ----
    float A[8];
    {
        uint4 raw = *(const uint4*)(g_Z + (size_t)P*NOUT + lane*8);
        __half2* h = (__half2*)&raw;
#pragma unroll
        for (int j = 0; j < 4; j++) {
            float2 f = __half22float2(h[j]);
            A[j*2+0] = f.x;
            A[j*2+1] = f.y;
        }
    }

    const int DS[5] = {1, 6, 12, 24, 36};
#pragma unroll
    for (int br = 0; br < 5; ++br) {
        int d = DS[br];
        const __half* zbr = g_Z + (size_t)n*NP*NOUT + (br+1)*256 + lane*8;
        uint4 raw[9];
        float wv[9];
#pragma unroll
        for (int k = 0; k < 9; k++) {
            int dy = (k/3 - 1)*d, dx = (k%3 - 1)*d;
            int ny = py + dy, nx = px + dx;
            bool ok = ((unsigned)ny < HH) && ((unsigned)nx < WW);
            int nyc = ok ? ny : py;          // clamp to own (always-valid) pixel
            int nxc = ok ? nx : px;
            raw[k] = *(const uint4*)(zbr + (size_t)(nyc*WW + nxc)*NOUT);
            wv[k]  = ok ? wsh[warp][br*9 + k] : 0.f;
        }
#pragma unroll
        for (int k = 0; k < 9; k++) h8_fma(A, raw[k], wv[k]);
    }

    // store y as fp16
    {
        __half* yr = g_yh + (size_t)P*CC + lane*8;
        uint4 packed;
        __half2* hp = (__half2*)&packed;
#pragma unroll
        for (int j = 0; j < 4; j++) hp[j] = __floats2half2_rn(A[j*2+0], A[j*2+1]);
        *(uint4*)yr = packed;
    }

    // fused BN stats: smem accumulate then one global atomic per channel
#pragma unroll
    for (int j = 0; j < 8; j++) {
        atomicAdd(&ssum[lane*8 + j], A[j]);
        atomicAdd(&ssq[lane*8 + j], A[j]*A[j]);
    }
    __syncthreads();
    if (warp < 4) {
        int c = tid;
        atomicAdd(&g_stats[c], ssum[c]);
        atomicAdd(&g_stats[256 + c], ssq[c]);
        c = tid + 128;
        atomicAdd(&g_stats[c], ssum[c]);
        atomicAdd(&g_stats[256 + c], ssq[c]);
    }
}

// ---------------- affine (inline BN finalize) + NHWC(fp16) -> NCHW(fp32) ----------------
__global__ void k_norm(float* __restrict__ out,
                       const float* __restrict__ gamma, const float* __restrict__ beta) {
    __shared__ float tile[32][33];
    __shared__ float sc[32], sh[32];
    int n  = blockIdx.z;
    int o0 = blockIdx.y * 32;
    int p0 = blockIdx.x * 32;
    int tx = threadIdx.x, ty = threadIdx.y;

    if (ty == 0) {
        int c = o0 + tx;
        float mean = g_stats[c] / NTOT;
        float var  = g_stats[256 + c] / NTOT - mean*mean;
        float rstd = rsqrtf(var + 1e-5f);
        float s = gamma[c] * rstd;
        sc[tx] = s;
        sh[tx] = beta[c] - mean*s;
    }
    __syncthreads();

#pragma unroll
    for (int i = 0; i < 4; i++) {
        int pl = ty + i*8;
        int oo = o0 + tx;
        float v = __half2float(g_yh[((size_t)n*NP + p0 + pl)*CC + oo]);
        tile[pl][tx] = v * sc[tx] + sh[tx];
    }
    __syncthreads();
#pragma unroll
    for (int i = 0; i < 4; i++) {
        int ol = ty + i*8;
        out[((size_t)(n*CC + o0 + ol))*NP + p0 + tx] = tile[tx][ol];
    }
}

// ---------------- launch ----------------
extern "C" void kernel_launch(void* const* d_in, const int* in_sizes, int n_in,
                              void* d_out, int out_size) {
    const float* x     = (const float*)d_in[0];
    const float* wcat  = (const float*)d_in[1];
    const float* wscl  = (const float*)d_in[2];
    const float* gamma = (const float*)d_in[3];
    const float* beta  = (const float*)d_in[4];
    float* out = (float*)d_out;

    cudaFuncSetAttribute(k_gemm, cudaFuncAttributeMaxDynamicSharedMemorySize, SM_TOTAL);

    {
        dim3 g(3, 96, NB*8), b(32, 8);
        k_pad_split<<<g, b>>>(x);
    }
    k_wsplit<<<(NOUT*CC)/256, 256>>>(wscl, wcat);
    {
        dim3 g(NP/128, NOUT/128, NB);
        k_gemm<<<g, 256, SM_TOTAL>>>();
    }
    k_gather<<<(NB*NP)/8, 256>>>();
    {
        dim3 g(NP/32, CC/32, NB), b(32, 8);
        k_norm<<<g, b>>>(out, gamma, beta);
    }
}